// round 10
// baseline (speedup 1.0000x reference)
#include <cuda_runtime.h>
#include <math.h>

// R10 resubmission: hashed x-pair folding via aligned float4 loads + predicated
// odd-lane fixup (R9 never benched: infra timeout).

#define NLV 16

// Exact rounded sizes of the dense (non-hashed) level slices:
// spatial levels 0-4: 4920+15632+42880+125000+373248 = 561680
// temporal levels 0-1: 83528+312504 = 396032
#define SPAIR_N 561680
#define TPAIR_N 396032

__device__ float4 g_spair[SPAIR_N];
__device__ float4 g_tpair[TPAIR_N];

struct LevelP {
  float    gm1s, gm1t;
  int      gm2s, gm2t;
  unsigned s_my, s_mz;
  unsigned t_my, t_mz, t_mw;
  unsigned s_off, t_off;
  int      s_hashed, t_hashed;
};
struct Params { LevelP lv[NLV]; };

// ---------------- pack kernel: build dense pair tables (runs every launch) ----------------
__global__ __launch_bounds__(256)
void pack_kernel(const float2* __restrict__ semb,
                 const float2* __restrict__ temb)
{
  int i = blockIdx.x * 256 + threadIdx.x;
  if (i < SPAIR_N) {
    float2 a = semb[i], b = semb[i + 1];
    g_spair[i] = make_float4(a.x, a.y, b.x, b.y);
  }
  if (i < TPAIR_N) {
    float2 a = temb[i], b = temb[i + 1];
    g_tpair[i] = make_float4(a.x, a.y, b.x, b.y);
  }
}

__device__ __forceinline__ float2 pick(const float4 v, unsigned p) {
  // p==0 -> row (x,y); p==1 -> row (z,w)
  return p ? make_float2(v.z, v.w) : make_float2(v.x, v.y);
}

__global__ __launch_bounds__(256)
void SpatialTemporalGridEncoder_kernel(
    const float4* __restrict__ in4,
    const float2* __restrict__ semb,
    const float2* __restrict__ temb,
    const float*  __restrict__ memb,
    float4* __restrict__ out,
    Params P, int B)
{
  int b = blockIdx.x * 256 + threadIdx.x;
  if (b >= B) return;
  float4 q = in4[b];

  // ---------------- mask: dense 128^3 trilinear + sigmoid ----------------
  float m;
  {
    float px = q.x * 127.f, py = q.y * 127.f, pz = q.z * 127.f;
    int ix = min((int)px, 126), iy = min((int)py, 126), iz = min((int)pz, 126);
    float fx = px - (float)ix, fy = py - (float)iy, fz = pz - (float)iz;
    float v[8];
#pragma unroll
    for (int c = 0; c < 8; c++) {
      unsigned xx = (unsigned)(ix + (c & 1));
      unsigned yy = (unsigned)(iy + ((c >> 1) & 1));
      unsigned zz = (unsigned)(iz + ((c >> 2) & 1));
      v[c] = __ldg(memb + xx + yy * 128u + zz * 16384u);
    }
    float acc = 0.f;
#pragma unroll
    for (int c = 0; c < 8; c++) {
      float w = ((c & 1) ? fx : 1.f - fx) *
                (((c >> 1) & 1) ? fy : 1.f - fy) *
                (((c >> 2) & 1) ? fz : 1.f - fz);
      acc += w * v[c];
    }
    m = 1.f / (1.f + __expf(-acc));
  }
  float one_m = 1.f - m;

  float4* orow = out + (size_t)b * 8;
  float4 pairout;

  // ---------------- 16 levels ----------------
#pragma unroll 1
  for (int l = 0; l < NLV; l++) {
    LevelP L = P.lv[l];
    float px = q.x * L.gm1s, py = q.y * L.gm1s, pz = q.z * L.gm1s, pw = q.w * L.gm1t;
    int ix = min((int)px, L.gm2s);
    int iy = min((int)py, L.gm2s);
    int iz = min((int)pz, L.gm2s);
    int iw = min((int)pw, L.gm2t);
    float fx = px - (float)ix, fy = py - (float)iy, fz = pz - (float)iz, fw = pw - (float)iw;
    float gx = 1.f - fx;

    unsigned ax0 = (unsigned)ix, ax1 = ax0 + 1u;
    bool oddx = (ix & 1) != 0;
    unsigned ay[2], az[2];
    ay[0] = (unsigned)iy * L.s_my;  ay[1] = ay[0] + L.s_my;
    az[0] = (unsigned)iz * L.s_mz;  az[1] = az[0] + L.s_mz;

    // ---- spatial ----
    float sx = 0.f, sy = 0.f;
    if (L.s_hashed) {
      const float4* st4 = (const float4*)(semb + L.s_off);
      unsigned iA[4], iB[4];
      float4 A[4], Bv[4];
#pragma unroll
      for (int c = 0; c < 4; c++) {
        unsigned h = ay[c & 1] ^ az[(c >> 1) & 1];
        iA[c] = (ax0 ^ h) & 0x7FFFFu;
        A[c] = __ldg(st4 + (iA[c] >> 1));
      }
#pragma unroll
      for (int c = 0; c < 4; c++) {
        unsigned h = ay[c & 1] ^ az[(c >> 1) & 1];
        iB[c] = (ax1 ^ h) & 0x7FFFFu;
        Bv[c] = A[c];
        if (oddx) Bv[c] = __ldg(st4 + (iB[c] >> 1));   // predicated: ~half lanes
      }
#pragma unroll
      for (int c = 0; c < 4; c++) {
        unsigned pA = iA[c] & 1u;
        unsigned pB = oddx ? (iB[c] & 1u) : (pA ^ 1u);
        float2 c0 = pick(A[c],  pA);
        float2 c1 = pick(Bv[c], pB);
        float wyz = ((c & 1) ? fy : 1.f - fy) * (((c >> 1) & 1) ? fz : 1.f - fz);
        sx += wyz * (gx * c0.x + fx * c1.x);
        sy += wyz * (gx * c0.y + fx * c1.y);
      }
    } else {
      const float4* sp = g_spair + L.s_off;
      float4 sv[4];
#pragma unroll
      for (int c = 0; c < 4; c++)
        sv[c] = __ldg(sp + (ax0 + ay[c & 1] + az[(c >> 1) & 1]));
#pragma unroll
      for (int c = 0; c < 4; c++) {
        float wyz = ((c & 1) ? fy : 1.f - fy) * (((c >> 1) & 1) ? fz : 1.f - fz);
        sx += wyz * (gx * sv[c].x + fx * sv[c].z);
        sy += wyz * (gx * sv[c].y + fx * sv[c].w);
      }
    }

    // ---- temporal ----
    unsigned by_[2], bz[2], bw[2];
    by_[0] = (unsigned)iy * L.t_my;  by_[1] = by_[0] + L.t_my;
    bz[0]  = (unsigned)iz * L.t_mz;  bz[1]  = bz[0] + L.t_mz;
    bw[0]  = (unsigned)iw * L.t_mw;  bw[1]  = bw[0] + L.t_mw;
    float tx = 0.f, ty = 0.f;
    if (L.t_hashed) {
      const float4* tt4 = (const float4*)(temb + L.t_off);
#pragma unroll
      for (int half = 0; half < 2; half++) {
        unsigned hw = bw[half];
        float wwt = half ? fw : 1.f - fw;
        unsigned iA[4], iB[4];
        float4 A[4], Bv[4];
#pragma unroll
        for (int c = 0; c < 4; c++) {
          unsigned h = by_[c & 1] ^ bz[(c >> 1) & 1] ^ hw;
          iA[c] = (ax0 ^ h) & 0x7FFFFu;
          A[c] = __ldg(tt4 + (iA[c] >> 1));
        }
#pragma unroll
        for (int c = 0; c < 4; c++) {
          unsigned h = by_[c & 1] ^ bz[(c >> 1) & 1] ^ hw;
          iB[c] = (ax1 ^ h) & 0x7FFFFu;
          Bv[c] = A[c];
          if (oddx) Bv[c] = __ldg(tt4 + (iB[c] >> 1));
        }
#pragma unroll
        for (int c = 0; c < 4; c++) {
          unsigned pA = iA[c] & 1u;
          unsigned pB = oddx ? (iB[c] & 1u) : (pA ^ 1u);
          float2 c0 = pick(A[c],  pA);
          float2 c1 = pick(Bv[c], pB);
          float w = wwt * ((c & 1) ? fy : 1.f - fy) * (((c >> 1) & 1) ? fz : 1.f - fz);
          tx += w * (gx * c0.x + fx * c1.x);
          ty += w * (gx * c0.y + fx * c1.y);
        }
      }
    } else {
      const float4* tp = g_tpair + L.t_off;
      float4 tv[8];
#pragma unroll
      for (int c = 0; c < 8; c++)
        tv[c] = __ldg(tp + (ax0 + by_[c & 1] + bz[(c >> 1) & 1] + bw[(c >> 2) & 1]));
#pragma unroll
      for (int c = 0; c < 8; c++) {
        float w = ((c & 1) ? fy : 1.f - fy) *
                  (((c >> 1) & 1) ? fz : 1.f - fz) *
                  (((c >> 2) & 1) ? fw : 1.f - fw);
        tx += w * (gx * tv[c].x + fx * tv[c].z);
        ty += w * (gx * tv[c].y + fx * tv[c].w);
      }
    }

    float ox = m * sx + one_m * tx;
    float oy = m * sy + one_m * ty;
    if ((l & 1) == 0) {
      pairout.x = ox; pairout.y = oy;
    } else {
      pairout.z = ox; pairout.w = oy;
      orow[l >> 1] = pairout;
    }
  }
}

// ---------------- host: level geometry (matches reference _level_grids) ----------------
static Params make_params() {
  Params P;
  const unsigned PR1 = 2654435761u, PR2 = 805459861u, PR3 = 3674653429u;
  unsigned soff = 0, toff = 0;
  for (int l = 0; l < NLV; l++) {
    long long srs = (long long)ceil(16.0 * pow(1.447, (double)l)) + 1;
    long long trs = (long long)ceil(16.0 * pow(1.15,  (double)l)) + 1;
    long long sprod = srs * srs * srs;
    long long tprod = sprod * trs;
    long long ssize = sprod < 524288LL ? sprod : 524288LL; ssize = ((ssize + 7) / 8) * 8;
    long long tsize = tprod < 524288LL ? tprod : 524288LL; tsize = ((tsize + 7) / 8) * 8;
    int sh = (sprod > ssize), th = (tprod > tsize);

    LevelP& L = P.lv[l];
    L.gm1s = (float)(srs - 1); L.gm1t = (float)(trs - 1);
    L.gm2s = (int)(srs - 2);   L.gm2t = (int)(trs - 2);
    L.s_my = sh ? PR1 : (unsigned)srs;
    L.s_mz = sh ? PR2 : (unsigned)(srs * srs);
    L.t_my = th ? PR1 : (unsigned)srs;
    L.t_mz = th ? PR2 : (unsigned)(srs * srs);
    L.t_mw = th ? PR3 : (unsigned)(srs * srs * srs);
    L.s_off = soff; L.t_off = toff;
    L.s_hashed = sh; L.t_hashed = th;
    soff += (unsigned)ssize; toff += (unsigned)tsize;
  }
  return P;
}

extern "C" void kernel_launch(void* const* d_in, const int* in_sizes, int n_in,
                              void* d_out, int out_size) {
  static const Params P = make_params();
  int B = in_sizes[0] / 4;
  const float4* in4  = (const float4*)d_in[0];
  const float2* semb = (const float2*)d_in[1];
  const float2* temb = (const float2*)d_in[2];
  const float*  memb = (const float*)d_in[3];
  float4* out = (float4*)d_out;

  pack_kernel<<<(SPAIR_N + 255) / 256, 256>>>(semb, temb);

  int blocks = (B + 255) / 256;
  SpatialTemporalGridEncoder_kernel<<<blocks, 256>>>(in4, semb, temb, memb, out, P, B);
}

// round 13
// speedup vs baseline: 1.1338x; 1.1338x over previous
#include <cuda_runtime.h>
#include <math.h>

// R13 resubmission: x-pair folding v2 — float4 base load + predicated float2 fixup,
// parity-swapped FFMA weights, regs capped for 5 CTAs/SM (R11/R12 never benched: infra).

#define NLV 16

#define SPAIR_N 561680
#define TPAIR_N 396032
#define MASK_N  2097152

__device__ float4 g_spair[SPAIR_N];
__device__ float4 g_tpair[TPAIR_N];
__device__ float2 g_mpair[MASK_N];

struct LevelP {
  float    gm1s, gm1t;
  int      gm2s, gm2t;
  unsigned s_my, s_mz;
  unsigned t_my, t_mz, t_mw;
  unsigned s_off, t_off;
  int      s_hashed, t_hashed;
};
struct Params { LevelP lv[NLV]; };

__global__ __launch_bounds__(256)
void pack_kernel(const float2* __restrict__ semb,
                 const float2* __restrict__ temb,
                 const float*  __restrict__ memb)
{
  int i = blockIdx.x * 256 + threadIdx.x;
  if (i < SPAIR_N) {
    float2 a = semb[i], b = semb[i + 1];
    g_spair[i] = make_float4(a.x, a.y, b.x, b.y);
  }
  if (i < TPAIR_N) {
    float2 a = temb[i], b = temb[i + 1];
    g_tpair[i] = make_float4(a.x, a.y, b.x, b.y);
  }
  if (i < MASK_N) {
    float a = memb[i];
    float b = (i + 1 < MASK_N) ? memb[i + 1] : 0.f;
    g_mpair[i] = make_float2(a, b);
  }
}

__global__ __launch_bounds__(256, 5)
void SpatialTemporalGridEncoder_kernel(
    const float4* __restrict__ in4,
    const float2* __restrict__ semb,
    const float2* __restrict__ temb,
    float4* __restrict__ out,
    Params P, int B)
{
  int b = blockIdx.x * 256 + threadIdx.x;
  if (b >= B) return;
  float4 q = in4[b];

  // ---------------- mask: dense 128^3 trilinear + sigmoid (4 paired loads) ----------------
  float m;
  {
    float px = q.x * 127.f, py = q.y * 127.f, pz = q.z * 127.f;
    int ix = min((int)px, 126), iy = min((int)py, 126), iz = min((int)pz, 126);
    float fx = px - (float)ix, fy = py - (float)iy, fz = pz - (float)iz;
    float2 v[4];
#pragma unroll
    for (int c = 0; c < 4; c++) {
      unsigned yy = (unsigned)(iy + (c & 1));
      unsigned zz = (unsigned)(iz + ((c >> 1) & 1));
      v[c] = __ldg(g_mpair + (unsigned)ix + yy * 128u + zz * 16384u);
    }
    float acc = 0.f;
#pragma unroll
    for (int c = 0; c < 4; c++) {
      float w = ((c & 1) ? fy : 1.f - fy) * (((c >> 1) & 1) ? fz : 1.f - fz);
      acc += w * ((1.f - fx) * v[c].x + fx * v[c].y);
    }
    m = 1.f / (1.f + __expf(-acc));
  }
  float one_m = 1.f - m;

  float4* orow = out + (size_t)b * 8;
  float4 pairout;

#pragma unroll 1
  for (int l = 0; l < NLV; l++) {
    LevelP L = P.lv[l];
    float px = q.x * L.gm1s, py = q.y * L.gm1s, pz = q.z * L.gm1s, pw = q.w * L.gm1t;
    int ix = min((int)px, L.gm2s);
    int iy = min((int)py, L.gm2s);
    int iz = min((int)pz, L.gm2s);
    int iw = min((int)pw, L.gm2t);
    float fx = px - (float)ix, fy = py - (float)iy, fz = pz - (float)iz, fw = pw - (float)iw;
    float gx = 1.f - fx;

    unsigned ax0 = (unsigned)ix, ax1 = ax0 + 1u;
    bool oddx = (ix & 1) != 0;
    float ev_fx  = oddx ? 0.f : fx;   // x1-weight applied to the base float4's other half
    float fx_odd = oddx ? fx : 0.f;   // x1-weight applied to the fixup row
    unsigned ay[2], az[2];
    ay[0] = (unsigned)iy * L.s_my;  ay[1] = ay[0] + L.s_my;
    az[0] = (unsigned)iz * L.s_mz;  az[1] = az[0] + L.s_mz;

    // ---- spatial ----
    float sx = 0.f, sy = 0.f;
    if (L.s_hashed) {
      const float4* st4 = (const float4*)(semb + L.s_off);
      const float2* st2 = semb + L.s_off;
      float4 A[4];
      float2 brow[4];
      unsigned pa[4];
#pragma unroll
      for (int c = 0; c < 4; c++) {
        unsigned h = ay[c & 1] ^ az[(c >> 1) & 1];
        unsigned iA = (ax0 ^ h) & 0x7FFFFu;
        pa[c] = iA & 1u;
        A[c] = __ldg(st4 + (iA >> 1));
      }
#pragma unroll
      for (int c = 0; c < 4; c++) {
        brow[c] = make_float2(0.f, 0.f);
        if (oddx) {
          unsigned h = ay[c & 1] ^ az[(c >> 1) & 1];
          brow[c] = __ldg(st2 + ((ax1 ^ h) & 0x7FFFFu));
        }
      }
#pragma unroll
      for (int c = 0; c < 4; c++) {
        float wa = pa[c] ? ev_fx : gx;
        float wb = pa[c] ? gx : ev_fx;
        float wyz = ((c & 1) ? fy : 1.f - fy) * (((c >> 1) & 1) ? fz : 1.f - fz);
        sx += wyz * (wa * A[c].x + wb * A[c].z + fx_odd * brow[c].x);
        sy += wyz * (wa * A[c].y + wb * A[c].w + fx_odd * brow[c].y);
      }
    } else {
      const float4* sp = g_spair + L.s_off;
      float4 sv[4];
#pragma unroll
      for (int c = 0; c < 4; c++)
        sv[c] = __ldg(sp + (ax0 + ay[c & 1] + az[(c >> 1) & 1]));
#pragma unroll
      for (int c = 0; c < 4; c++) {
        float wyz = ((c & 1) ? fy : 1.f - fy) * (((c >> 1) & 1) ? fz : 1.f - fz);
        sx += wyz * (gx * sv[c].x + fx * sv[c].z);
        sy += wyz * (gx * sv[c].y + fx * sv[c].w);
      }
    }

    // ---- temporal ----
    unsigned by_[2], bz[2], bw[2];
    by_[0] = (unsigned)iy * L.t_my;  by_[1] = by_[0] + L.t_my;
    bz[0]  = (unsigned)iz * L.t_mz;  bz[1]  = bz[0] + L.t_mz;
    bw[0]  = (unsigned)iw * L.t_mw;  bw[1]  = bw[0] + L.t_mw;
    float tx = 0.f, ty = 0.f;
    if (L.t_hashed) {
      const float4* tt4 = (const float4*)(temb + L.t_off);
      const float2* tt2 = temb + L.t_off;
#pragma unroll
      for (int half = 0; half < 2; half++) {
        unsigned hw = bw[half];
        float wwt = half ? fw : 1.f - fw;
        float4 A[4];
        float2 brow[4];
        unsigned pa[4];
#pragma unroll
        for (int c = 0; c < 4; c++) {
          unsigned h = by_[c & 1] ^ bz[(c >> 1) & 1] ^ hw;
          unsigned iA = (ax0 ^ h) & 0x7FFFFu;
          pa[c] = iA & 1u;
          A[c] = __ldg(tt4 + (iA >> 1));
        }
#pragma unroll
        for (int c = 0; c < 4; c++) {
          brow[c] = make_float2(0.f, 0.f);
          if (oddx) {
            unsigned h = by_[c & 1] ^ bz[(c >> 1) & 1] ^ hw;
            brow[c] = __ldg(tt2 + ((ax1 ^ h) & 0x7FFFFu));
          }
        }
#pragma unroll
        for (int c = 0; c < 4; c++) {
          float wa = pa[c] ? ev_fx : gx;
          float wb = pa[c] ? gx : ev_fx;
          float w = wwt * ((c & 1) ? fy : 1.f - fy) * (((c >> 1) & 1) ? fz : 1.f - fz);
          tx += w * (wa * A[c].x + wb * A[c].z + fx_odd * brow[c].x);
          ty += w * (wa * A[c].y + wb * A[c].w + fx_odd * brow[c].y);
        }
      }
    } else {
      const float4* tp = g_tpair + L.t_off;
      float4 tv[8];
#pragma unroll
      for (int c = 0; c < 8; c++)
        tv[c] = __ldg(tp + (ax0 + by_[c & 1] + bz[(c >> 1) & 1] + bw[(c >> 2) & 1]));
#pragma unroll
      for (int c = 0; c < 8; c++) {
        float w = ((c & 1) ? fy : 1.f - fy) *
                  (((c >> 1) & 1) ? fz : 1.f - fz) *
                  (((c >> 2) & 1) ? fw : 1.f - fw);
        tx += w * (gx * tv[c].x + fx * tv[c].z);
        ty += w * (gx * tv[c].y + fx * tv[c].w);
      }
    }

    float ox = m * sx + one_m * tx;
    float oy = m * sy + one_m * ty;
    if ((l & 1) == 0) {
      pairout.x = ox; pairout.y = oy;
    } else {
      pairout.z = ox; pairout.w = oy;
      orow[l >> 1] = pairout;
    }
  }
}

// ---------------- host: level geometry (matches reference _level_grids) ----------------
static Params make_params() {
  Params P;
  const unsigned PR1 = 2654435761u, PR2 = 805459861u, PR3 = 3674653429u;
  unsigned soff = 0, toff = 0;
  for (int l = 0; l < NLV; l++) {
    long long srs = (long long)ceil(16.0 * pow(1.447, (double)l)) + 1;
    long long trs = (long long)ceil(16.0 * pow(1.15,  (double)l)) + 1;
    long long sprod = srs * srs * srs;
    long long tprod = sprod * trs;
    long long ssize = sprod < 524288LL ? sprod : 524288LL; ssize = ((ssize + 7) / 8) * 8;
    long long tsize = tprod < 524288LL ? tprod : 524288LL; tsize = ((tsize + 7) / 8) * 8;
    int sh = (sprod > ssize), th = (tprod > tsize);

    LevelP& L = P.lv[l];
    L.gm1s = (float)(srs - 1); L.gm1t = (float)(trs - 1);
    L.gm2s = (int)(srs - 2);   L.gm2t = (int)(trs - 2);
    L.s_my = sh ? PR1 : (unsigned)srs;
    L.s_mz = sh ? PR2 : (unsigned)(srs * srs);
    L.t_my = th ? PR1 : (unsigned)srs;
    L.t_mz = th ? PR2 : (unsigned)(srs * srs);
    L.t_mw = th ? PR3 : (unsigned)(srs * srs * srs);
    L.s_off = soff; L.t_off = toff;
    L.s_hashed = sh; L.t_hashed = th;
    soff += (unsigned)ssize; toff += (unsigned)tsize;
  }
  return P;
}

extern "C" void kernel_launch(void* const* d_in, const int* in_sizes, int n_in,
                              void* d_out, int out_size) {
  static const Params P = make_params();
  int B = in_sizes[0] / 4;
  const float4* in4  = (const float4*)d_in[0];
  const float2* semb = (const float2*)d_in[1];
  const float2* temb = (const float2*)d_in[2];
  const float*  memb = (const float*)d_in[3];
  float4* out = (float4*)d_out;

  pack_kernel<<<(MASK_N + 255) / 256, 256>>>(semb, temb, memb);

  int blocks = (B + 255) / 256;
  SpatialTemporalGridEncoder_kernel<<<blocks, 256>>>(in4, semb, temb, out, P, B);
}